// round 14
// baseline (speedup 1.0000x reference)
#include <cuda_runtime.h>
#include <math.h>
#include <cstdint>
#include <cuda_fp16.h>

#define S_LEN    4096
#define DM       1024
#define NHEADS   16
#define HDIM     64

// Scratch (allocation-free rule: __device__ globals)
__device__ __half g_Xh[S_LEN * DM];
__device__ __half g_Wh[4 * DM * DM];
__device__ __half g_Qh[S_LEN * DM];
__device__ __half g_Kh[S_LEN * DM];
__device__ __half g_Vh[S_LEN * DM];
__device__ __half g_Ah[S_LEN * DM];
__device__ float2 g_cs[S_LEN * 32];        // (cos, sin) per (pos, j)

struct OutPtrs { void* p[3]; };
struct SrcPtrs { const float2* p[5]; };

// ===========================================================================
// Helpers
// ===========================================================================
__device__ __forceinline__ uint32_t smem_u32(const void* p) {
    uint32_t a;
    asm("{ .reg .u64 t; cvta.to.shared.u64 t, %1; cvt.u32.u64 %0, t; }"
        : "=r"(a) : "l"(p));
    return a;
}
__device__ __forceinline__ void cp_async16(uint32_t s, const void* g) {
    asm volatile("cp.async.cg.shared.global [%0], [%1], 16;" :: "r"(s), "l"(g));
}
#define CP_ASYNC_COMMIT()  asm volatile("cp.async.commit_group;" ::: "memory")
#define CP_ASYNC_WAIT(n)   asm volatile("cp.async.wait_group %0;" :: "n"(n) : "memory")

__device__ __forceinline__ void mma_f16(float* c, uint32_t a0, uint32_t a1,
                                        uint32_t a2, uint32_t a3,
                                        uint32_t b0, uint32_t b1) {
    asm volatile(
        "mma.sync.aligned.m16n8k16.row.col.f32.f16.f16.f32 "
        "{%0,%1,%2,%3}, {%4,%5,%6,%7}, {%8,%9}, {%0,%1,%2,%3};"
        : "+f"(c[0]), "+f"(c[1]), "+f"(c[2]), "+f"(c[3])
        : "r"(a0), "r"(a1), "r"(a2), "r"(a3), "r"(b0), "r"(b1));
}
__device__ __forceinline__ void ldmatrix_x4(uint32_t& r0, uint32_t& r1,
                                            uint32_t& r2, uint32_t& r3, uint32_t addr) {
    asm volatile("ldmatrix.sync.aligned.m8n8.x4.shared.b16 {%0,%1,%2,%3}, [%4];"
                 : "=r"(r0), "=r"(r1), "=r"(r2), "=r"(r3) : "r"(addr));
}
__device__ __forceinline__ void ldmatrix_x4_trans(uint32_t& r0, uint32_t& r1,
                                                  uint32_t& r2, uint32_t& r3, uint32_t addr) {
    asm volatile("ldmatrix.sync.aligned.m8n8.x4.trans.shared.b16 {%0,%1,%2,%3}, [%4];"
                 : "=r"(r0), "=r"(r1), "=r"(r2), "=r"(r3) : "r"(addr));
}
// pack (x, y) to half2, then 2^x in packed fp16
__device__ __forceinline__ uint32_t ex2_h2(float x, float y) {
    __half2 h = __floats2half2_rn(x, y);
    uint32_t d = *(uint32_t*)&h;
    uint32_t p;
    asm("ex2.approx.f16x2 %0, %1;" : "=r"(p) : "r"(d));
    return p;
}

// ===========================================================================
// Single prep launch: fp16 conversion of x + 4 weights, plus cos/sin table
// ===========================================================================
#define NX2 (S_LEN * DM / 2)
#define NW2 (DM * DM / 2)
#define NALL2 (NX2 + 4 * NW2)
#define NCS (S_LEN * 32)
#define NPREP (NALL2 + NCS)

__global__ __launch_bounds__(256) void prep_kernel(SrcPtrs srcs, const int* __restrict__ pos)
{
    int i = blockIdx.x * blockDim.x + threadIdx.x;
    if (i < NALL2) {
        float2 v;
        __half2* dst;
        if (i < NX2) {
            v = srcs.p[0][i];
            dst = (__half2*)g_Xh + i;
        } else {
            int rel = i - NX2;
            int w = rel / NW2;
            int off = rel - w * NW2;
            v = srcs.p[1 + w][off];
            dst = (__half2*)g_Wh + w * NW2 + off;
        }
        *dst = __floats2half2_rn(v.x, v.y);
    } else if (i < NPREP) {
        int idx = i - NALL2;
        int s = idx >> 5;
        int j = idx & 31;
        double invf = exp(-(double)j / 32.0 * log(10000.0));
        float ang = (float)pos[s] * (float)invf;
        float sn, cs;
        sincosf(ang, &sn, &cs);
        g_cs[idx] = make_float2(cs, sn);
    }
}

// ===========================================================================
// fp16 mma.sync GEMM (NT), fp32 accumulate, 128x128x32h tile, 256 threads.
// 3-stage cp.async pipeline (two tiles in flight behind compute).
// ROPE=true fuses RoPE into the epilogue; Q additionally gets the
// (1/8)*log2(e) prescale so flash softmax runs in base 2.
// ===========================================================================
#define HBM 128
#define HBN 128
#define HBK 32
#define HKT (DM / HBK)               // 32
#define HSTR 40
#define HG_AS (HBM * HSTR)           // halves per A stage (5120)
#define HG_BS (HBN * HSTR)
#define HG_SMEM (3 * (HG_AS + HG_BS) * 2)   // 61440 B

template <typename OutT, bool ROPE>
__global__ __launch_bounds__(256) void hgemm(
    const __half* __restrict__ A, const __half* __restrict__ B, OutPtrs outs)
{
    extern __shared__ __align__(16) __half hsm[];
    __half* Ah = hsm;                      // [3][HG_AS]
    __half* Bh = hsm + 3 * HG_AS;          // [3][HG_BS]
    const uint32_t ah_u = smem_u32(Ah);
    const uint32_t bh_u = smem_u32(Bh);

    const int tid  = threadIdx.x;
    const int wid  = tid >> 5;
    const int lane = tid & 31;
    const int wm   = wid >> 1;
    const int wn   = wid & 1;
    const int r    = lane >> 2;
    const int c4   = lane & 3;
    const int row0  = blockIdx.y * HBM;
    const int col0g = blockIdx.x * HBN;

    const int mat = col0g >> 10;
    OutT* C = (OutT*)outs.p[mat];
    const int colW = col0g & (DM - 1);

    const int lrow = ((lane >> 3) & 1) * 8 + (lane & 7);
    const int lcol = ((lane >> 4) & 1) * 8;

    float acc[2][8][4];
#pragma unroll
    for (int mt = 0; mt < 2; mt++)
#pragma unroll
        for (int nt = 0; nt < 8; nt++)
#pragma unroll
            for (int i = 0; i < 4; i++) acc[mt][nt][i] = 0.f;

    auto load_tile = [&](int kt, int buf) {
        const int k0 = kt * HBK;
#pragma unroll
        for (int i = 0; i < 2; i++) {
            int chunk = tid + i * 256;
            int m = chunk >> 2, c8 = (chunk & 3) * 8;
            cp_async16(ah_u + (uint32_t)(((buf * HG_AS) + m * HSTR + c8) * 2),
                       A + (size_t)(row0 + m) * DM + k0 + c8);
        }
#pragma unroll
        for (int i = 0; i < 2; i++) {
            int chunk = tid + i * 256;
            int m = chunk >> 2, c8 = (chunk & 3) * 8;
            cp_async16(bh_u + (uint32_t)(((buf * HG_BS) + m * HSTR + c8) * 2),
                       B + (size_t)(col0g + m) * DM + k0 + c8);
        }
        CP_ASYNC_COMMIT();
    };

    load_tile(0, 0);
    load_tile(1, 1);

    for (int kt = 0; kt < HKT; kt++) {
        const int buf = kt % 3;
        if (kt < HKT - 1) { CP_ASYNC_WAIT(1); } else { CP_ASYNC_WAIT(0); }
        __syncthreads();
        if (kt + 2 < HKT) load_tile(kt + 2, (kt + 2) % 3);

#pragma unroll
        for (int s = 0; s < 2; s++) {
            const int k0 = s * 16;
            uint32_t au[2][4], bu[8][2];
#pragma unroll
            for (int mt = 0; mt < 2; mt++) {
                int row = wm * 32 + mt * 16 + lrow;
                uint32_t addr = ah_u +
                    (uint32_t)((buf * HG_AS + row * HSTR + k0 + lcol) * 2);
                ldmatrix_x4(au[mt][0], au[mt][1], au[mt][2], au[mt][3], addr);
            }
#pragma unroll
            for (int ntp = 0; ntp < 4; ntp++) {
                int row = wn * 64 + ntp * 16 + lrow;
                uint32_t addr = bh_u +
                    (uint32_t)((buf * HG_BS + row * HSTR + k0 + lcol) * 2);
                uint32_t t0, t1, t2, t3;
                ldmatrix_x4(t0, t1, t2, t3, addr);
                bu[2 * ntp][0] = t0;     bu[2 * ntp][1] = t2;
                bu[2 * ntp + 1][0] = t1; bu[2 * ntp + 1][1] = t3;
            }
#pragma unroll
            for (int mt = 0; mt < 2; mt++)
#pragma unroll
                for (int nt = 0; nt < 8; nt++)
                    mma_f16(acc[mt][nt], au[mt][0], au[mt][1], au[mt][2], au[mt][3],
                            bu[nt][0], bu[nt][1]);
        }
    }

    const bool do_rope = ROPE && (mat < 2);
    // Q: 1/8 softmax scale folded with log2(e) for base-2 softmax in flash
    const float qs = (mat == 0) ? 0.125f * 1.4426950408889634f : 1.0f;

#pragma unroll
    for (int mt = 0; mt < 2; mt++) {
#pragma unroll
        for (int nt = 0; nt < 8; nt++) {
            int row = row0 + wm * 32 + mt * 16 + r;
            int col = colW + wn * 64 + nt * 8 + c4 * 2;
            float v0 = acc[mt][nt][0], v1 = acc[mt][nt][1];
            float v2 = acc[mt][nt][2], v3 = acc[mt][nt][3];
            if (do_rope) {
                int j = nt * 4 + c4;
                float2 csA = g_cs[row * 32 + j];
                float2 csB = g_cs[(row + 8) * 32 + j];
                float t0 = v0 * csA.x - v1 * csA.y;
                float t1 = v0 * csA.y + v1 * csA.x;
                float t2 = v2 * csB.x - v3 * csB.y;
                float t3 = v2 * csB.y + v3 * csB.x;
                v0 = t0 * qs; v1 = t1 * qs; v2 = t2 * qs; v3 = t3 * qs;
            }
            if (sizeof(OutT) == 4) {
                *(float2*)((float*)C + (size_t)row * DM + col) = make_float2(v0, v1);
                *(float2*)((float*)C + (size_t)(row + 8) * DM + col) = make_float2(v2, v3);
            } else {
                *(__half2*)((__half*)C + (size_t)row * DM + col) =
                    __floats2half2_rn(v0, v1);
                *(__half2*)((__half*)C + (size_t)(row + 8) * DM + col) =
                    __floats2half2_rn(v2, v3);
            }
        }
    }
}

// ===========================================================================
// fp16 causal flash attention. Bq=128 (8 warps x 16 queries), Bc=64.
// Base-2 softmax with packed ex2.approx.f16x2 (P born as fp16 A-frags);
// row-sum l via extra MMA against an all-ones B-frag. (R9 config — 143us.)
// ===========================================================================
#define FSTR 72
#define H2_ONES 0x3C003C00u

__global__ __launch_bounds__(256) void flash_h(
    const __half* __restrict__ Q, const __half* __restrict__ K,
    const __half* __restrict__ V, __half* __restrict__ O)
{
    __shared__ __align__(16) __half Ks[2][64][FSTR];
    __shared__ __align__(16) __half Vs[2][64][FSTR];
    const uint32_t ks_u = smem_u32(Ks);
    const uint32_t vs_u = smem_u32(Vs);

    const int tid  = threadIdx.x;
    const int warp = tid >> 5;       // 0..7
    const int lane = tid & 31;
    const int r    = lane >> 2;
    const int c    = lane & 3;
    const int qblk = (gridDim.x >> 4) - 1 - (int)(blockIdx.x >> 4);  // heavy first
    const int h    = blockIdx.x & 15;
    const int qbase = qblk * 128;
    const int w16   = warp * 16;
    const int lrow  = ((lane >> 3) & 1) * 8 + (lane & 7);
    const int lcol  = ((lane >> 4) & 1) * 8;

    // ---- stage 128 Q rows across both Ks buffers, extract A-frags ---------
    for (int i = 0; i < 4; i++) {
        int chunk = tid + i * 256;
        int row = chunk >> 3, c8 = (chunk & 7) * 8;     // row 0..127
        *(float4*)&Ks[0][0][row * FSTR + c8] =
            *(const float4*)(Q + (size_t)(qbase + row) * DM + h * HDIM + c8);
    }
    __syncthreads();

    uint32_t qa[4][4];
#pragma unroll
    for (int g = 0; g < 4; g++) {
        uint32_t addr = ks_u + (uint32_t)(((w16 + lrow) * FSTR + g * 16 + lcol) * 2);
        ldmatrix_x4(qa[g][0], qa[g][1], qa[g][2], qa[g][3], addr);
    }
    __syncthreads();

    auto load_tile = [&](int buf, int kt) {
#pragma unroll
        for (int i = 0; i < 2; i++) {
            int chunk = tid + i * 256;
            int row = chunk >> 3, c8 = (chunk & 7) * 8;
            cp_async16(ks_u + (uint32_t)(((buf * 64 + row) * FSTR + c8) * 2),
                       K + (size_t)(kt + row) * DM + h * HDIM + c8);
        }
#pragma unroll
        for (int i = 0; i < 2; i++) {
            int chunk = tid + i * 256;
            int row = chunk >> 3, c8 = (chunk & 7) * 8;
            cp_async16(vs_u + (uint32_t)(((buf * 64 + row) * FSTR + c8) * 2),
                       V + (size_t)(kt + row) * DM + h * HDIM + c8);
        }
        CP_ASYNC_COMMIT();
    };

    float acc[8][4];
#pragma unroll
    for (int nt = 0; nt < 8; nt++)
#pragma unroll
        for (int i = 0; i < 4; i++) acc[nt][i] = 0.f;
    float m0 = -1e30f, m1 = -1e30f, l0 = 0.f, l1 = 0.f;

    load_tile(0, 0);
    const int kend = qbase + 128;

    for (int kt = 0; kt < kend; kt += 64) {
        const int buf = (kt >> 6) & 1;
        CP_ASYNC_WAIT(0);
        __syncthreads();
        if (kt + 64 < kend) load_tile(buf ^ 1, kt + 64);

        // warp fully above the diagonal on this tile -> nothing visible
        if (kt > qbase + w16 + 15) continue;

        const uint32_t kb_u = ks_u + (uint32_t)(buf * 64 * FSTR * 2);
        const uint32_t vb_u = vs_u + (uint32_t)(buf * 64 * FSTR * 2);

        // ---- S = Q K^T (already log2-scaled via Q) -------------------------
        float sc[8][4];
#pragma unroll
        for (int nt = 0; nt < 8; nt++)
            sc[nt][0] = sc[nt][1] = sc[nt][2] = sc[nt][3] = 0.f;
#pragma unroll
        for (int g = 0; g < 4; g++) {
#pragma unroll
            for (int ntp = 0; ntp < 4; ntp++) {
                uint32_t addr = kb_u +
                    (uint32_t)(((ntp * 16 + lrow) * FSTR + g * 16 + lcol) * 2);
                uint32_t t0, t1, t2, t3;
                ldmatrix_x4(t0, t1, t2, t3, addr);
                mma_f16(sc[2 * ntp],     qa[g][0], qa[g][1], qa[g][2], qa[g][3], t0, t2);
                mma_f16(sc[2 * ntp + 1], qa[g][0], qa[g][1], qa[g][2], qa[g][3], t1, t3);
            }
        }

        // ---- causal mask (diagonal tiles only) -----------------------------
        if (kt + 63 > qbase + w16) {
            const int thr0 = qbase + w16 + r - kt;     // max visible local col
            const int thr1 = thr0 + 8;
#pragma unroll
            for (int nt = 0; nt < 8; nt++) {
                int cb = nt * 8 + 2 * c;
                if (cb     > thr0) sc[nt][0] = -1e30f;
                if (cb + 1 > thr0) sc[nt][1] = -1e30f;
                if (cb     > thr1) sc[nt][2] = -1e30f;
                if (cb + 1 > thr1) sc[nt][3] = -1e30f;
            }
        }

        // ---- online max (base-2 domain) ------------------------------------
        float mx0 = -1e30f, mx1 = -1e30f;
#pragma unroll
        for (int nt = 0; nt < 8; nt++) {
            mx0 = fmaxf(mx0, fmaxf(sc[nt][0], sc[nt][1]));
            mx1 = fmaxf(mx1, fmaxf(sc[nt][2], sc[nt][3]));
        }
        mx0 = fmaxf(mx0, __shfl_xor_sync(0xffffffffu, mx0, 1));
        mx0 = fmaxf(mx0, __shfl_xor_sync(0xffffffffu, mx0, 2));
        mx1 = fmaxf(mx1, __shfl_xor_sync(0xffffffffu, mx1, 1));
        mx1 = fmaxf(mx1, __shfl_xor_sync(0xffffffffu, mx1, 2));

        float nm0 = fmaxf(m0, mx0), nm1 = fmaxf(m1, mx1);
        float s0 = exp2f(m0 - nm0), s1 = exp2f(m1 - nm1);
        m0 = nm0; m1 = nm1;
        l0 *= s0; l1 *= s1;
#pragma unroll
        for (int nt = 0; nt < 8; nt++) {
            acc[nt][0] *= s0; acc[nt][1] *= s0;
            acc[nt][2] *= s1; acc[nt][3] *= s1;
        }

        // ---- P = ex2(sc - m) in packed fp16; PV + row-sum MMAs -------------
        float lacc[4] = {0.f, 0.f, 0.f, 0.f};
#pragma unroll
        for (int kk = 0; kk < 4; kk++) {
            uint32_t a0 = ex2_h2(sc[2 * kk][0] - m0,     sc[2 * kk][1] - m0);
            uint32_t a1 = ex2_h2(sc[2 * kk][2] - m1,     sc[2 * kk][3] - m1);
            uint32_t a2 = ex2_h2(sc[2 * kk + 1][0] - m0, sc[2 * kk + 1][1] - m0);
            uint32_t a3 = ex2_h2(sc[2 * kk + 1][2] - m1, sc[2 * kk + 1][3] - m1);

            mma_f16(lacc, a0, a1, a2, a3, H2_ONES, H2_ONES);   // row sums

            const int vrow = kk * 16 + (lane & 15);
            const int vcolsel = (lane >> 4) & 1;
#pragma unroll
            for (int ndp = 0; ndp < 4; ndp++) {
                uint32_t baddr = vb_u +
                    (uint32_t)((vrow * FSTR + (2 * ndp + vcolsel) * 8) * 2);
                uint32_t b0, b1, b2, b3;
                ldmatrix_x4_trans(b0, b1, b2, b3, baddr);
                mma_f16(acc[2 * ndp],     a0, a1, a2, a3, b0, b1);
                mma_f16(acc[2 * ndp + 1], a0, a1, a2, a3, b2, b3);
            }
        }
        l0 += lacc[0];
        l1 += lacc[2];
    }

    // ---- epilogue ---------------------------------------------------------
    float i0 = 1.f / l0, i1 = 1.f / l1;
    const int row0 = qbase + w16 + r;
#pragma unroll
    for (int nt = 0; nt < 8; nt++) {
        int col = h * HDIM + nt * 8 + 2 * c;
        *(__half2*)&O[(size_t)row0 * DM + col] =
            __floats2half2_rn(acc[nt][0] * i0, acc[nt][1] * i0);
        *(__half2*)&O[(size_t)(row0 + 8) * DM + col] =
            __floats2half2_rn(acc[nt][2] * i1, acc[nt][3] * i1);
    }
}

// ---------------------------------------------------------------------------
// Launcher
// ---------------------------------------------------------------------------
extern "C" void kernel_launch(void* const* d_in, const int* in_sizes, int n_in,
                              void* d_out, int out_size)
{
    const float* x  = (const float*)d_in[0];
    const int*  pos = (const int*)  d_in[5];
    float* out = (float*)d_out;

    __half *Xh, *Wh, *Qh, *Kh, *Vh, *Ah;
    cudaGetSymbolAddress((void**)&Xh, g_Xh);
    cudaGetSymbolAddress((void**)&Wh, g_Wh);
    cudaGetSymbolAddress((void**)&Qh, g_Qh);
    cudaGetSymbolAddress((void**)&Kh, g_Kh);
    cudaGetSymbolAddress((void**)&Vh, g_Vh);
    cudaGetSymbolAddress((void**)&Ah, g_Ah);

    cudaFuncSetAttribute((const void*)hgemm<__half, true>,
                         cudaFuncAttributeMaxDynamicSharedMemorySize, HG_SMEM);
    cudaFuncSetAttribute((const void*)hgemm<float, false>,
                         cudaFuncAttributeMaxDynamicSharedMemorySize, HG_SMEM);

    SrcPtrs srcs;
    srcs.p[0] = (const float2*)x;
    srcs.p[1] = (const float2*)d_in[1];
    srcs.p[2] = (const float2*)d_in[2];
    srcs.p[3] = (const float2*)d_in[3];
    srcs.p[4] = (const float2*)d_in[4];
    prep_kernel<<<(NPREP + 255) / 256, 256>>>(srcs, pos);

    // merged QKV GEMM with fused RoPE (+ base-2 Q prescale) epilogue
    OutPtrs qkv; qkv.p[0] = Qh; qkv.p[1] = Kh; qkv.p[2] = Vh;
    dim3 qkv_grid(3 * DM / HBN, S_LEN / HBM);     // (24, 32)
    hgemm<__half, true><<<qkv_grid, 256, HG_SMEM>>>(Xh, Wh, qkv);

    flash_h<<<(S_LEN / 128) * NHEADS, 256>>>(Qh, Kh, Vh, Ah);

    OutPtrs op; op.p[0] = out; op.p[1] = out; op.p[2] = out;
    dim3 out_grid(DM / HBN, S_LEN / HBM);         // (8, 32)
    hgemm<float, false><<<out_grid, 256, HG_SMEM>>>(Ah, Wh + 3 * DM * DM, op);
}

// round 15
// speedup vs baseline: 1.0865x; 1.0865x over previous
#include <cuda_runtime.h>
#include <math.h>
#include <cstdint>
#include <cuda_fp16.h>

#define S_LEN    4096
#define DM       1024
#define NHEADS   16
#define HDIM     64

// Scratch (allocation-free rule: __device__ globals)
__device__ __half g_Xh[S_LEN * DM];
__device__ __half g_Wh[4 * DM * DM];
__device__ __half g_Qh[S_LEN * DM];
__device__ __half g_Kh[S_LEN * DM];
__device__ __half g_Vh[S_LEN * DM];
__device__ __half g_Ah[S_LEN * DM];
__device__ float2 g_cs[S_LEN * 32];        // (cos, sin) per (pos, j)

struct OutPtrs { void* p[3]; };
struct SrcPtrs { const float2* p[5]; };

// ===========================================================================
// Helpers
// ===========================================================================
__device__ __forceinline__ uint32_t smem_u32(const void* p) {
    uint32_t a;
    asm("{ .reg .u64 t; cvta.to.shared.u64 t, %1; cvt.u32.u64 %0, t; }"
        : "=r"(a) : "l"(p));
    return a;
}
__device__ __forceinline__ void cp_async16(uint32_t s, const void* g) {
    asm volatile("cp.async.cg.shared.global [%0], [%1], 16;" :: "r"(s), "l"(g));
}
#define CP_ASYNC_COMMIT()  asm volatile("cp.async.commit_group;" ::: "memory")
#define CP_ASYNC_WAIT(n)   asm volatile("cp.async.wait_group %0;" :: "n"(n) : "memory")

__device__ __forceinline__ void mma_f16(float* c, uint32_t a0, uint32_t a1,
                                        uint32_t a2, uint32_t a3,
                                        uint32_t b0, uint32_t b1) {
    asm volatile(
        "mma.sync.aligned.m16n8k16.row.col.f32.f16.f16.f32 "
        "{%0,%1,%2,%3}, {%4,%5,%6,%7}, {%8,%9}, {%0,%1,%2,%3};"
        : "+f"(c[0]), "+f"(c[1]), "+f"(c[2]), "+f"(c[3])
        : "r"(a0), "r"(a1), "r"(a2), "r"(a3), "r"(b0), "r"(b1));
}
__device__ __forceinline__ void ldmatrix_x4(uint32_t& r0, uint32_t& r1,
                                            uint32_t& r2, uint32_t& r3, uint32_t addr) {
    asm volatile("ldmatrix.sync.aligned.m8n8.x4.shared.b16 {%0,%1,%2,%3}, [%4];"
                 : "=r"(r0), "=r"(r1), "=r"(r2), "=r"(r3) : "r"(addr));
}
__device__ __forceinline__ void ldmatrix_x4_trans(uint32_t& r0, uint32_t& r1,
                                                  uint32_t& r2, uint32_t& r3, uint32_t addr) {
    asm volatile("ldmatrix.sync.aligned.m8n8.x4.trans.shared.b16 {%0,%1,%2,%3}, [%4];"
                 : "=r"(r0), "=r"(r1), "=r"(r2), "=r"(r3) : "r"(addr));
}
// pack (x, y) to half2, then 2^x in packed fp16
__device__ __forceinline__ uint32_t ex2_h2(float x, float y) {
    __half2 h = __floats2half2_rn(x, y);
    uint32_t d = *(uint32_t*)&h;
    uint32_t p;
    asm("ex2.approx.f16x2 %0, %1;" : "=r"(p) : "r"(d));
    return p;
}

// ===========================================================================
// Single prep launch: fp16 conversion of x + 4 weights, plus cos/sin table
// ===========================================================================
#define NX2 (S_LEN * DM / 2)
#define NW2 (DM * DM / 2)
#define NALL2 (NX2 + 4 * NW2)
#define NCS (S_LEN * 32)
#define NPREP (NALL2 + NCS)

__global__ __launch_bounds__(256) void prep_kernel(SrcPtrs srcs, const int* __restrict__ pos)
{
    int i = blockIdx.x * blockDim.x + threadIdx.x;
    if (i < NALL2) {
        float2 v;
        __half2* dst;
        if (i < NX2) {
            v = srcs.p[0][i];
            dst = (__half2*)g_Xh + i;
        } else {
            int rel = i - NX2;
            int w = rel / NW2;
            int off = rel - w * NW2;
            v = srcs.p[1 + w][off];
            dst = (__half2*)g_Wh + w * NW2 + off;
        }
        *dst = __floats2half2_rn(v.x, v.y);
    } else if (i < NPREP) {
        int idx = i - NALL2;
        int s = idx >> 5;
        int j = idx & 31;
        double invf = exp(-(double)j / 32.0 * log(10000.0));
        float ang = (float)pos[s] * (float)invf;
        float sn, cs;
        sincosf(ang, &sn, &cs);
        g_cs[idx] = make_float2(cs, sn);
    }
}

// ===========================================================================
// fp16 mma.sync GEMM (NT), fp32 accumulate.
// 128x128x64h k-tiles (16 iterations, HALF the barriers of BK=32);
// per iteration per warp: 24 ldmatrix + 64 MMA. Double-buffered cp.async,
// 72KB dynamic smem, 2 CTAs/SM.
// ROPE=true fuses RoPE into the epilogue; Q additionally gets the
// (1/8)*log2(e) prescale so flash softmax runs in base 2.
// ===========================================================================
#define HBM 128
#define HBN 128
#define HBK 64                        // halves per k-tile
#define HKT (DM / HBK)                // 16
#define HSTR 72                       // row stride (halves), pad 8
#define HG_AS (HBM * HSTR)            // halves per A stage (9216)
#define HG_BS (HBN * HSTR)
#define HG_SMEM (2 * (HG_AS + HG_BS) * 2)   // 73728 B

template <typename OutT, bool ROPE>
__global__ __launch_bounds__(256) void hgemm(
    const __half* __restrict__ A, const __half* __restrict__ B, OutPtrs outs)
{
    extern __shared__ __align__(16) __half hsm[];
    __half* Ah = hsm;                      // [2][HG_AS]
    __half* Bh = hsm + 2 * HG_AS;          // [2][HG_BS]
    const uint32_t ah_u = smem_u32(Ah);
    const uint32_t bh_u = smem_u32(Bh);

    const int tid  = threadIdx.x;
    const int wid  = tid >> 5;
    const int lane = tid & 31;
    const int wm   = wid >> 1;
    const int wn   = wid & 1;
    const int r    = lane >> 2;
    const int c4   = lane & 3;
    const int row0  = blockIdx.y * HBM;
    const int col0g = blockIdx.x * HBN;

    const int mat = col0g >> 10;
    OutT* C = (OutT*)outs.p[mat];
    const int colW = col0g & (DM - 1);

    const int lrow = ((lane >> 3) & 1) * 8 + (lane & 7);
    const int lcol = ((lane >> 4) & 1) * 8;

    float acc[2][8][4];
#pragma unroll
    for (int mt = 0; mt < 2; mt++)
#pragma unroll
        for (int nt = 0; nt < 8; nt++)
#pragma unroll
            for (int i = 0; i < 4; i++) acc[mt][nt][i] = 0.f;

    auto load_tile = [&](int kt, int buf) {
        const int k0 = kt * HBK;
#pragma unroll
        for (int i = 0; i < 4; i++) {             // A: 1024 x 16B chunks
            int chunk = tid + i * 256;
            int m = chunk >> 3, c8 = (chunk & 7) * 8;
            cp_async16(ah_u + (uint32_t)((buf * HG_AS + m * HSTR + c8) * 2),
                       A + (size_t)(row0 + m) * DM + k0 + c8);
        }
#pragma unroll
        for (int i = 0; i < 4; i++) {             // B: 1024 x 16B chunks
            int chunk = tid + i * 256;
            int m = chunk >> 3, c8 = (chunk & 7) * 8;
            cp_async16(bh_u + (uint32_t)((buf * HG_BS + m * HSTR + c8) * 2),
                       B + (size_t)(col0g + m) * DM + k0 + c8);
        }
        CP_ASYNC_COMMIT();
    };

    load_tile(0, 0);

    for (int kt = 0; kt < HKT; kt++) {
        const int buf = kt & 1;
        CP_ASYNC_WAIT(0);
        __syncthreads();
        if (kt + 1 < HKT) load_tile(kt + 1, buf ^ 1);

#pragma unroll
        for (int s = 0; s < 4; s++) {             // four k16 steps per k-tile
            const int k0 = s * 16;
            uint32_t au[2][4], bu[8][2];
#pragma unroll
            for (int mt = 0; mt < 2; mt++) {
                int row = wm * 32 + mt * 16 + lrow;
                uint32_t addr = ah_u +
                    (uint32_t)((buf * HG_AS + row * HSTR + k0 + lcol) * 2);
                ldmatrix_x4(au[mt][0], au[mt][1], au[mt][2], au[mt][3], addr);
            }
#pragma unroll
            for (int ntp = 0; ntp < 4; ntp++) {
                int row = wn * 64 + ntp * 16 + lrow;
                uint32_t addr = bh_u +
                    (uint32_t)((buf * HG_BS + row * HSTR + k0 + lcol) * 2);
                uint32_t t0, t1, t2, t3;
                ldmatrix_x4(t0, t1, t2, t3, addr);
                bu[2 * ntp][0] = t0;     bu[2 * ntp][1] = t2;
                bu[2 * ntp + 1][0] = t1; bu[2 * ntp + 1][1] = t3;
            }
#pragma unroll
            for (int mt = 0; mt < 2; mt++)
#pragma unroll
                for (int nt = 0; nt < 8; nt++)
                    mma_f16(acc[mt][nt], au[mt][0], au[mt][1], au[mt][2], au[mt][3],
                            bu[nt][0], bu[nt][1]);
        }
    }

    const bool do_rope = ROPE && (mat < 2);
    // Q: 1/8 softmax scale folded with log2(e) for base-2 softmax in flash
    const float qs = (mat == 0) ? 0.125f * 1.4426950408889634f : 1.0f;

#pragma unroll
    for (int mt = 0; mt < 2; mt++) {
#pragma unroll
        for (int nt = 0; nt < 8; nt++) {
            int row = row0 + wm * 32 + mt * 16 + r;
            int col = colW + wn * 64 + nt * 8 + c4 * 2;
            float v0 = acc[mt][nt][0], v1 = acc[mt][nt][1];
            float v2 = acc[mt][nt][2], v3 = acc[mt][nt][3];
            if (do_rope) {
                int j = nt * 4 + c4;
                float2 csA = g_cs[row * 32 + j];
                float2 csB = g_cs[(row + 8) * 32 + j];
                float t0 = v0 * csA.x - v1 * csA.y;
                float t1 = v0 * csA.y + v1 * csA.x;
                float t2 = v2 * csB.x - v3 * csB.y;
                float t3 = v2 * csB.y + v3 * csB.x;
                v0 = t0 * qs; v1 = t1 * qs; v2 = t2 * qs; v3 = t3 * qs;
            }
            if (sizeof(OutT) == 4) {
                *(float2*)((float*)C + (size_t)row * DM + col) = make_float2(v0, v1);
                *(float2*)((float*)C + (size_t)(row + 8) * DM + col) = make_float2(v2, v3);
            } else {
                *(__half2*)((__half*)C + (size_t)row * DM + col) =
                    __floats2half2_rn(v0, v1);
                *(__half2*)((__half*)C + (size_t)(row + 8) * DM + col) =
                    __floats2half2_rn(v2, v3);
            }
        }
    }
}

// ===========================================================================
// fp16 causal flash attention. Bq=128 (8 warps x 16 queries), Bc=64.
// Base-2 softmax with packed ex2.approx.f16x2 (P born as fp16 A-frags);
// row-sum l via extra MMA against an all-ones B-frag. (R9 config — 143us.)
// ===========================================================================
#define FSTR 72
#define H2_ONES 0x3C003C00u

__global__ __launch_bounds__(256) void flash_h(
    const __half* __restrict__ Q, const __half* __restrict__ K,
    const __half* __restrict__ V, __half* __restrict__ O)
{
    __shared__ __align__(16) __half Ks[2][64][FSTR];
    __shared__ __align__(16) __half Vs[2][64][FSTR];
    const uint32_t ks_u = smem_u32(Ks);
    const uint32_t vs_u = smem_u32(Vs);

    const int tid  = threadIdx.x;
    const int warp = tid >> 5;       // 0..7
    const int lane = tid & 31;
    const int r    = lane >> 2;
    const int c    = lane & 3;
    const int qblk = (gridDim.x >> 4) - 1 - (int)(blockIdx.x >> 4);  // heavy first
    const int h    = blockIdx.x & 15;
    const int qbase = qblk * 128;
    const int w16   = warp * 16;
    const int lrow  = ((lane >> 3) & 1) * 8 + (lane & 7);
    const int lcol  = ((lane >> 4) & 1) * 8;

    // ---- stage 128 Q rows across both Ks buffers, extract A-frags ---------
    for (int i = 0; i < 4; i++) {
        int chunk = tid + i * 256;
        int row = chunk >> 3, c8 = (chunk & 7) * 8;     // row 0..127
        *(float4*)&Ks[0][0][row * FSTR + c8] =
            *(const float4*)(Q + (size_t)(qbase + row) * DM + h * HDIM + c8);
    }
    __syncthreads();

    uint32_t qa[4][4];
#pragma unroll
    for (int g = 0; g < 4; g++) {
        uint32_t addr = ks_u + (uint32_t)(((w16 + lrow) * FSTR + g * 16 + lcol) * 2);
        ldmatrix_x4(qa[g][0], qa[g][1], qa[g][2], qa[g][3], addr);
    }
    __syncthreads();

    auto load_tile = [&](int buf, int kt) {
#pragma unroll
        for (int i = 0; i < 2; i++) {
            int chunk = tid + i * 256;
            int row = chunk >> 3, c8 = (chunk & 7) * 8;
            cp_async16(ks_u + (uint32_t)(((buf * 64 + row) * FSTR + c8) * 2),
                       K + (size_t)(kt + row) * DM + h * HDIM + c8);
        }
#pragma unroll
        for (int i = 0; i < 2; i++) {
            int chunk = tid + i * 256;
            int row = chunk >> 3, c8 = (chunk & 7) * 8;
            cp_async16(vs_u + (uint32_t)(((buf * 64 + row) * FSTR + c8) * 2),
                       V + (size_t)(kt + row) * DM + h * HDIM + c8);
        }
        CP_ASYNC_COMMIT();
    };

    float acc[8][4];
#pragma unroll
    for (int nt = 0; nt < 8; nt++)
#pragma unroll
        for (int i = 0; i < 4; i++) acc[nt][i] = 0.f;
    float m0 = -1e30f, m1 = -1e30f, l0 = 0.f, l1 = 0.f;

    load_tile(0, 0);
    const int kend = qbase + 128;

    for (int kt = 0; kt < kend; kt += 64) {
        const int buf = (kt >> 6) & 1;
        CP_ASYNC_WAIT(0);
        __syncthreads();
        if (kt + 64 < kend) load_tile(buf ^ 1, kt + 64);

        // warp fully above the diagonal on this tile -> nothing visible
        if (kt > qbase + w16 + 15) continue;

        const uint32_t kb_u = ks_u + (uint32_t)(buf * 64 * FSTR * 2);
        const uint32_t vb_u = vs_u + (uint32_t)(buf * 64 * FSTR * 2);

        // ---- S = Q K^T (already log2-scaled via Q) -------------------------
        float sc[8][4];
#pragma unroll
        for (int nt = 0; nt < 8; nt++)
            sc[nt][0] = sc[nt][1] = sc[nt][2] = sc[nt][3] = 0.f;
#pragma unroll
        for (int g = 0; g < 4; g++) {
#pragma unroll
            for (int ntp = 0; ntp < 4; ntp++) {
                uint32_t addr = kb_u +
                    (uint32_t)(((ntp * 16 + lrow) * FSTR + g * 16 + lcol) * 2);
                uint32_t t0, t1, t2, t3;
                ldmatrix_x4(t0, t1, t2, t3, addr);
                mma_f16(sc[2 * ntp],     qa[g][0], qa[g][1], qa[g][2], qa[g][3], t0, t2);
                mma_f16(sc[2 * ntp + 1], qa[g][0], qa[g][1], qa[g][2], qa[g][3], t1, t3);
            }
        }

        // ---- causal mask (diagonal tiles only) -----------------------------
        if (kt + 63 > qbase + w16) {
            const int thr0 = qbase + w16 + r - kt;     // max visible local col
            const int thr1 = thr0 + 8;
#pragma unroll
            for (int nt = 0; nt < 8; nt++) {
                int cb = nt * 8 + 2 * c;
                if (cb     > thr0) sc[nt][0] = -1e30f;
                if (cb + 1 > thr0) sc[nt][1] = -1e30f;
                if (cb     > thr1) sc[nt][2] = -1e30f;
                if (cb + 1 > thr1) sc[nt][3] = -1e30f;
            }
        }

        // ---- online max (base-2 domain) ------------------------------------
        float mx0 = -1e30f, mx1 = -1e30f;
#pragma unroll
        for (int nt = 0; nt < 8; nt++) {
            mx0 = fmaxf(mx0, fmaxf(sc[nt][0], sc[nt][1]));
            mx1 = fmaxf(mx1, fmaxf(sc[nt][2], sc[nt][3]));
        }
        mx0 = fmaxf(mx0, __shfl_xor_sync(0xffffffffu, mx0, 1));
        mx0 = fmaxf(mx0, __shfl_xor_sync(0xffffffffu, mx0, 2));
        mx1 = fmaxf(mx1, __shfl_xor_sync(0xffffffffu, mx1, 1));
        mx1 = fmaxf(mx1, __shfl_xor_sync(0xffffffffu, mx1, 2));

        float nm0 = fmaxf(m0, mx0), nm1 = fmaxf(m1, mx1);
        float s0 = exp2f(m0 - nm0), s1 = exp2f(m1 - nm1);
        m0 = nm0; m1 = nm1;
        l0 *= s0; l1 *= s1;
#pragma unroll
        for (int nt = 0; nt < 8; nt++) {
            acc[nt][0] *= s0; acc[nt][1] *= s0;
            acc[nt][2] *= s1; acc[nt][3] *= s1;
        }

        // ---- P = ex2(sc - m) in packed fp16; PV + row-sum MMAs -------------
        float lacc[4] = {0.f, 0.f, 0.f, 0.f};
#pragma unroll
        for (int kk = 0; kk < 4; kk++) {
            uint32_t a0 = ex2_h2(sc[2 * kk][0] - m0,     sc[2 * kk][1] - m0);
            uint32_t a1 = ex2_h2(sc[2 * kk][2] - m1,     sc[2 * kk][3] - m1);
            uint32_t a2 = ex2_h2(sc[2 * kk + 1][0] - m0, sc[2 * kk + 1][1] - m0);
            uint32_t a3 = ex2_h2(sc[2 * kk + 1][2] - m1, sc[2 * kk + 1][3] - m1);

            mma_f16(lacc, a0, a1, a2, a3, H2_ONES, H2_ONES);   // row sums

            const int vrow = kk * 16 + (lane & 15);
            const int vcolsel = (lane >> 4) & 1;
#pragma unroll
            for (int ndp = 0; ndp < 4; ndp++) {
                uint32_t baddr = vb_u +
                    (uint32_t)((vrow * FSTR + (2 * ndp + vcolsel) * 8) * 2);
                uint32_t b0, b1, b2, b3;
                ldmatrix_x4_trans(b0, b1, b2, b3, baddr);
                mma_f16(acc[2 * ndp],     a0, a1, a2, a3, b0, b1);
                mma_f16(acc[2 * ndp + 1], a0, a1, a2, a3, b2, b3);
            }
        }
        l0 += lacc[0];
        l1 += lacc[2];
    }

    // ---- epilogue ---------------------------------------------------------
    float i0 = 1.f / l0, i1 = 1.f / l1;
    const int row0 = qbase + w16 + r;
#pragma unroll
    for (int nt = 0; nt < 8; nt++) {
        int col = h * HDIM + nt * 8 + 2 * c;
        *(__half2*)&O[(size_t)row0 * DM + col] =
            __floats2half2_rn(acc[nt][0] * i0, acc[nt][1] * i0);
        *(__half2*)&O[(size_t)(row0 + 8) * DM + col] =
            __floats2half2_rn(acc[nt][2] * i1, acc[nt][3] * i1);
    }
}

// ---------------------------------------------------------------------------
// Launcher
// ---------------------------------------------------------------------------
extern "C" void kernel_launch(void* const* d_in, const int* in_sizes, int n_in,
                              void* d_out, int out_size)
{
    const float* x  = (const float*)d_in[0];
    const int*  pos = (const int*)  d_in[5];
    float* out = (float*)d_out;

    __half *Xh, *Wh, *Qh, *Kh, *Vh, *Ah;
    cudaGetSymbolAddress((void**)&Xh, g_Xh);
    cudaGetSymbolAddress((void**)&Wh, g_Wh);
    cudaGetSymbolAddress((void**)&Qh, g_Qh);
    cudaGetSymbolAddress((void**)&Kh, g_Kh);
    cudaGetSymbolAddress((void**)&Vh, g_Vh);
    cudaGetSymbolAddress((void**)&Ah, g_Ah);

    cudaFuncSetAttribute((const void*)hgemm<__half, true>,
                         cudaFuncAttributeMaxDynamicSharedMemorySize, HG_SMEM);
    cudaFuncSetAttribute((const void*)hgemm<float, false>,
                         cudaFuncAttributeMaxDynamicSharedMemorySize, HG_SMEM);

    SrcPtrs srcs;
    srcs.p[0] = (const float2*)x;
    srcs.p[1] = (const float2*)d_in[1];
    srcs.p[2] = (const float2*)d_in[2];
    srcs.p[3] = (const float2*)d_in[3];
    srcs.p[4] = (const float2*)d_in[4];
    prep_kernel<<<(NPREP + 255) / 256, 256>>>(srcs, pos);

    // merged QKV GEMM with fused RoPE (+ base-2 Q prescale) epilogue
    OutPtrs qkv; qkv.p[0] = Qh; qkv.p[1] = Kh; qkv.p[2] = Vh;
    dim3 qkv_grid(3 * DM / HBN, S_LEN / HBM);     // (24, 32)
    hgemm<__half, true><<<qkv_grid, 256, HG_SMEM>>>(Xh, Wh, qkv);

    flash_h<<<(S_LEN / 128) * NHEADS, 256>>>(Qh, Kh, Vh, Ah);

    OutPtrs op; op.p[0] = out; op.p[1] = out; op.p[2] = out;
    dim3 out_grid(DM / HBN, S_LEN / HBM);         // (8, 32)
    hgemm<float, false><<<out_grid, 256, HG_SMEM>>>(Ah, Wh + 3 * DM * DM, op);
}